// round 14
// baseline (speedup 1.0000x reference)
#include <cuda_runtime.h>
#include <cstdint>

// Problem constants
#define BB 4096
#define NN 8192
#define THREADS 256
#define VECW 8
#define CTAS_PER_ROW 4
#define CHUNK (NN / CTAS_PER_ROW)               // 2048 elements per CTA
// THREADS * VECW == CHUNK  -> exactly one fully-unrolled batch per thread

#define TAU_SYN_INV 0.5f
#define TAU_MEM_INV 0.5f
#define V_TH 1.0f
#define V_RESET 0.0f
#define INHIB (-5.0f)

// Per-row winner slot: (bits(v_new) << 32) | (0xFFFFFFFF - index).
// v_new >= 1.0 for any spiked element -> high word >= 0x3F800000 iff the row
// spiked. Positive-float bits are order-monotone; complemented index gives
// first-max (smallest index wins ties). Zero at module load; phase2 resets
// after consuming, so every graph replay sees zeros.
__device__ unsigned long long g_winner[BB];

__device__ __forceinline__ void argmax_combine(float& bv, int& bi, float ov, int oi) {
    if (ov > bv || (ov == bv && oi < bi)) { bv = ov; bi = oi; }
}

// ---- 256-bit global accesses (sm_100+/sm_103a: LDG.E.256 / STG.E.256) ----
__device__ __forceinline__ void ldg256_cs(const float* p, unsigned u[8]) {
    asm volatile("ld.global.cs.v8.b32 {%0,%1,%2,%3,%4,%5,%6,%7}, [%8];"
                 : "=r"(u[0]), "=r"(u[1]), "=r"(u[2]), "=r"(u[3]),
                   "=r"(u[4]), "=r"(u[5]), "=r"(u[6]), "=r"(u[7])
                 : "l"(p));
}
__device__ __forceinline__ void stg256_cs(float* p, const unsigned u[8]) {
    asm volatile("st.global.cs.v8.b32 [%0], {%1,%2,%3,%4,%5,%6,%7,%8};"
                 :: "l"(p),
                    "r"(u[0]), "r"(u[1]), "r"(u[2]), "r"(u[3]),
                    "r"(u[4]), "r"(u[5]), "r"(u[6]), "r"(u[7])
                 : "memory");
}

// ---------------------------------------------------------------------------
// Kernel 1: barrier-free streaming pass, 4 CTAs/row, 256-bit accesses.
//   writes i_new, z, v_out = INHIB prefill; merges per-warp argmax candidates
//   into g_winner[row] via atomicMax (no return -> REDG).
// ---------------------------------------------------------------------------
__global__ void __launch_bounds__(THREADS, 6)
lif_phase1(const float* __restrict__ x,
           const float* __restrict__ v,
           const float* __restrict__ icur,
           float* __restrict__ z_out,
           float* __restrict__ v_out,
           float* __restrict__ i_out) {
    const int cta     = blockIdx.x;
    const int row     = cta >> 2;          // CTAS_PER_ROW = 4
    const int quarter = cta & 3;
    const int t       = threadIdx.x;
    const int lane    = t & 31;

    const size_t base = (size_t)row * NN + (size_t)quarter * CHUNK;
    const int    goff = quarter * CHUNK + t * VECW;   // this thread's first row index
    const size_t off  = base + (size_t)t * VECW;      // 32B-aligned (t*8 floats)

    // front-batched 256-bit loads: maximal MLP, no loop carry
    unsigned xu[8], vu[8], cu[8];
    ldg256_cs(x    + off, xu);
    ldg256_cs(v    + off, vu);
    ldg256_cs(icur + off, cu);

    // overlapped constant prefill of v_out (independent of the loads)
    unsigned inh[8];
    #pragma unroll
    for (int c = 0; c < 8; c++) inh[c] = __float_as_uint(INHIB);
    stg256_cs(v_out + off, inh);

    const float NEG_INF = __int_as_float(0xff800000u);
    float best = NEG_INF;
    int   bidx = 0x7fffffff;

    unsigned iu[8], zu[8];
    #pragma unroll
    for (int c = 0; c < VECW; c++) {
        float xf = __uint_as_float(xu[c]);
        float vf = __uint_as_float(vu[c]);
        float cf = __uint_as_float(cu[c]);
        float inew = cf + TAU_SYN_INV * (xf - cf);
        float vnew = vf + TAU_MEM_INV * (inew - vf);
        float zc   = (vnew >= V_TH) ? 1.0f : 0.0f;
        iu[c] = __float_as_uint(inew);
        zu[c] = __float_as_uint(zc);
        if (zc > 0.0f) {
            argmax_combine(best, bidx, vnew, goff + c);
        }
    }
    stg256_cs(i_out + off, iu);
    stg256_cs(z_out + off, zu);

    // warp argmax (first-max semantics), then one RED per spiking warp
    #pragma unroll
    for (int s = 16; s > 0; s >>= 1) {
        float ov = __shfl_xor_sync(0xffffffffu, best, s);
        int   oi = __shfl_xor_sync(0xffffffffu, bidx, s);
        argmax_combine(best, bidx, ov, oi);
    }
    if (lane == 0 && best >= V_TH) {
        unsigned long long packed =
            ((unsigned long long)__float_as_uint(best) << 32) |
            (unsigned long long)(0xFFFFFFFFu - (unsigned)bidx);
        atomicMax(&g_winner[row], packed);   // result unused -> REDG
    }

#if __CUDA_ARCH__ >= 900
    cudaTriggerProgrammaticLaunchCompletion();
#endif
}

// ---------------------------------------------------------------------------
// Kernel 2 (PDL): per-row fix-up. Winner spiked -> v_after(winner) = 0;
// everything else already holds INHIB. Rare no-spike row: rewrite with v_new.
// Resets the slot for the next graph replay.
// ---------------------------------------------------------------------------
__global__ void lif_phase2(const float* __restrict__ v,
                           const float* __restrict__ i_out,
                           float* __restrict__ v_out) {
#if __CUDA_ARCH__ >= 900
    cudaGridDependencySynchronize();       // phase1 stores + REDs visible
#endif
    const int row = blockIdx.x * blockDim.x + threadIdx.x;
    if (row >= BB) return;

    unsigned long long slot = __ldcg(&g_winner[row]);
    g_winner[row] = 0ULL;                  // reset for next replay

    const unsigned vb = (unsigned)(slot >> 32);
    const size_t base = (size_t)row * NN;

    if (vb >= 0x3F800000u) {               // any spike in row
        const unsigned widx = 0xFFFFFFFFu - (unsigned)slot;
        v_out[base + widx] = V_RESET;
    } else {
        // No spikes: v_out = v_new (no resets, no inhibition). Rare; scalar ok.
        for (int n = 0; n < NN; n++) {
            float vv = v[base + n];
            float iv = i_out[base + n];
            v_out[base + n] = vv + TAU_MEM_INV * (iv - vv);
        }
    }
}

extern "C" void kernel_launch(void* const* d_in, const int* in_sizes, int n_in,
                              void* d_out, int out_size) {
    const float* x = (const float*)d_in[0];
    const float* v = (const float*)d_in[1];
    const float* i = (const float*)d_in[2];

    float* out   = (float*)d_out;
    float* z_out = out;                           // [B, N]
    float* v_out = out + (size_t)BB * NN;         // [B, N]
    float* i_out = out + 2 * (size_t)BB * NN;     // [B, N]

    lif_phase1<<<BB * CTAS_PER_ROW, THREADS>>>(x, v, i, z_out, v_out, i_out);

    // Phase 2 via Programmatic Dependent Launch: launch setup and block
    // dispatch overlap phase1's tail; the grid-dependency sync inside
    // provides ordering + memory visibility.
    cudaLaunchAttribute attrs[1];
    attrs[0].id = cudaLaunchAttributeProgrammaticStreamSerialization;
    attrs[0].val.programmaticStreamSerializationAllowed = 1;

    cudaLaunchConfig_t cfg = {};
    cfg.gridDim  = dim3(64, 1, 1);
    cfg.blockDim = dim3(64, 1, 1);
    cfg.dynamicSmemBytes = 0;
    cfg.stream   = 0;                      // capture stream
    cfg.attrs    = attrs;
    cfg.numAttrs = 1;

    cudaLaunchKernelEx(&cfg, lif_phase2, v, i_out, v_out);
}